// round 4
// baseline (speedup 1.0000x reference)
#include <cuda_runtime.h>
#include <cuda_fp16.h>
#include <cstdint>

#define PP 3
#define CC 32
#define HH 256
#define WW 256
#define HW (HH * WW)

// Transposed, x-pair-interleaved fp16 texture:
//   layout: [P][y][x>>1][c][x&1]  (block per x-pair = 64 halves = 128B line)
__device__ __align__(16) __half g_tex[PP * HW * CC];
__device__ float g_inv[PP * 9];
__device__ float g_scale;

// ---------------------------------------------------------------------------
// Transpose [P][C][HW] fp32 -> interleaved fp16 layout above.
// Block = 256 threads, tile = 64 hw (32 x-pairs, single y) x 32 ch.
// Block (0,0) thread 0 also computes plane inverses + scale.
// ---------------------------------------------------------------------------
__global__ void __launch_bounds__(256) transpose_kernel(
    const float* __restrict__ in,
    const float* __restrict__ planes,
    const int* __restrict__ bw_raw) {
    if (blockIdx.x == 0 && blockIdx.y == 0 && threadIdx.x == 0) {
        int bits = bw_raw[0];
        float bw;
        if (bits > 0 && bits < 1000000) bw = (float)bits;          // int payload
        else                            bw = __int_as_float(bits); // float payload
        g_scale = 2.0f / bw;

        for (int p = 0; p < PP; p++) {
            const float* a = planes + p * 9;
            float a00=a[0],a01=a[1],a02=a[2];
            float a10=a[3],a11=a[4],a12=a[5];
            float a20=a[6],a21=a[7],a22=a[8];
            float c00 =  (a11*a22 - a12*a21);
            float c01 = -(a10*a22 - a12*a20);
            float c02 =  (a10*a21 - a11*a20);
            float c10 = -(a01*a22 - a02*a21);
            float c11 =  (a00*a22 - a02*a20);
            float c12 = -(a00*a21 - a01*a20);
            float c20 =  (a01*a12 - a02*a11);
            float c21 = -(a00*a12 - a02*a10);
            float c22 =  (a00*a11 - a01*a10);
            float det = a00*c00 + a01*c01 + a02*c02;
            float id  = 1.0f / det;
            float* o = g_inv + p * 9;
            o[0]=c00*id; o[1]=c10*id; o[2]=c20*id;
            o[3]=c01*id; o[4]=c11*id; o[5]=c21*id;
            o[6]=c02*id; o[7]=c12*id; o[8]=c22*id;
        }
    }

    __shared__ float tile[CC][65];       // 64 hw + pad
    int p   = blockIdx.y;
    int ib  = blockIdx.x * 64;           // hw tile base (64-aligned -> one y)
    int tid = threadIdx.x;

    // Phase 1: read 32ch x 64hw as float4 (coalesced along hw)
    const float4* in4 = (const float4*)in + (size_t)p * CC * (HW / 4);
    int f = tid & 15;                    // float4 index within 64 hw
    int c = tid >> 4;                    // channel 0..15
    #pragma unroll
    for (int r = 0; r < 2; r++) {
        int cc = c + r * 16;
        float4 v = __ldg(in4 + (size_t)cc * (HW / 4) + (ib >> 2) + f);
        tile[cc][4*f + 0] = v.x;
        tile[cc][4*f + 1] = v.y;
        tile[cc][4*f + 2] = v.z;
        tile[cc][4*f + 3] = v.w;
    }
    __syncthreads();

    // Phase 2: write half2 = (ch c @ x even, ch c @ x odd); lanes sweep c
    // -> each warp emits full 128B lines.
    int y   = ib >> 8;
    int xb2 = (ib & 255) >> 1;           // x-pair base within row
    int cw  = tid & 31;                  // channel
    int pr0 = tid >> 5;                  // pair 0..7
    __half2* dst = (__half2*)g_tex + (size_t)p * (HW * 16);
    #pragma unroll
    for (int r = 0; r < 4; r++) {
        int pair = pr0 + r * 8;          // 0..31
        __half2 h = __floats2half2_rn(tile[cw][2*pair], tile[cw][2*pair + 1]);
        dst[(size_t)y * 4096 + (size_t)(xb2 + pair) * 32 + cw] = h;
    }
}

// ---------------------------------------------------------------------------
// Sampler: 8 lanes per (plane, point); lane q handles channels 4q..4q+3.
// One 16B load per row delivers (west,east) interleaved for those channels;
// odd-x0 points take a predicated second load + PRMT byte-select. Bilinear is
// fully in-lane: no shuffles.
// ---------------------------------------------------------------------------
__device__ __forceinline__ unsigned prmt(unsigned a, unsigned b, unsigned s) {
    unsigned d;
    asm("prmt.b32 %0, %1, %2, %3;" : "=r"(d) : "r"(a), "r"(b), "r"(s));
    return d;
}
__device__ __forceinline__ float2 h2f(unsigned u) {
    return __half22float2(*reinterpret_cast<__half2*>(&u));
}

__global__ void __launch_bounds__(256) sample_kernel(
    const float* __restrict__ coords, float* __restrict__ out, int M) {
    int t  = blockIdx.x * blockDim.x + threadIdx.x;
    int pm = t >> 3;
    int q  = t & 7;
    if (pm >= PP * M) return;

    int p = (pm >= 2*M) ? 2 : (pm >= M ? 1 : 0);
    int m = pm - p * M;

    float s = g_scale;
    const float* cp2 = coords + 3 * m;
    float x = __ldg(cp2)     * s;
    float y = __ldg(cp2 + 1) * s;
    float z = __ldg(cp2 + 2) * s;

    const float* inv = g_inv + p * 9;
    float u = x * inv[0] + y * inv[3] + z * inv[6];
    float v = x * inv[1] + y * inv[4] + z * inv[7];

    float ix = (u + 1.0f) * (0.5f * (WW - 1));
    float iy = (v + 1.0f) * (0.5f * (HH - 1));
    float fx = floorf(ix), fy = floorf(iy);

    float wxe = ix - fx;
    float wxw = (fx + 1.0f) - ix;
    float wys = iy - fy;
    float wyn = (fy + 1.0f) - iy;

    int fxi = (int)fx;
    int fyi = (int)fy;
    // x clamp folded onto the in-bounds adjacent pair
    if (fxi > WW - 2) { wxe = wxw + wxe; wxw = 0.0f; }
    if (fxi < 0)      { wxw = wxw + wxe; wxe = 0.0f; }
    int bx = min(max(fxi, 0), WW - 2);
    int y0 = min(max(fyi,     0), HH - 1);
    int y1 = min(max(fyi + 1, 0), HH - 1);

    float c0w = wyn * wxw, c0e = wyn * wxe;   // row y0 folded weights
    float c1w = wys * wxw, c1e = wys * wxe;   // row y1

    int par = bx & 1;
    int xb  = bx >> 1;
    unsigned sel = par ? 0x5432u : 0x3210u;

    // uint4 view: 4 uint4 per 64B half-block; block(y,xb) = 8 uint4, 128B line
    const uint4* tex = (const uint4*)g_tex + (size_t)p * (HW * 4);
    size_t i0 = ((size_t)y0 * 128 + xb) * 8 + q;
    size_t i1 = ((size_t)y1 * 128 + xb) * 8 + q;
    uint4 a0 = __ldg(tex + i0);
    uint4 a1 = __ldg(tex + i1);
    uint4 b0 = a0, b1 = a1;
    if (par) {                     // straddles two blocks (predicated loads)
        b0 = __ldg(tex + i0 + 8);
        b1 = __ldg(tex + i1 + 8);
    }

    float2 f0, f1;
    float4 r;
    f0 = h2f(prmt(a0.x, b0.x, sel)); f1 = h2f(prmt(a1.x, b1.x, sel));
    r.x = c0w*f0.x + c0e*f0.y + c1w*f1.x + c1e*f1.y;
    f0 = h2f(prmt(a0.y, b0.y, sel)); f1 = h2f(prmt(a1.y, b1.y, sel));
    r.y = c0w*f0.x + c0e*f0.y + c1w*f1.x + c1e*f1.y;
    f0 = h2f(prmt(a0.z, b0.z, sel)); f1 = h2f(prmt(a1.z, b1.z, sel));
    r.z = c0w*f0.x + c0e*f0.y + c1w*f1.x + c1e*f1.y;
    f0 = h2f(prmt(a0.w, b0.w, sel)); f1 = h2f(prmt(a1.w, b1.w, sel));
    r.w = c0w*f0.x + c0e*f0.y + c1w*f1.x + c1e*f1.y;

    // lane q owns channels 4q..4q+3 -> dense 128B store per point
    ((float4*)(out + (size_t)pm * CC))[q] = r;
}

// ---------------------------------------------------------------------------
extern "C" void kernel_launch(void* const* d_in, const int* in_sizes, int n_in,
                              void* d_out, int out_size) {
    const float* feats  = (const float*)d_in[0];   // [1,3,32,256,256] fp32
    const float* coords = (const float*)d_in[1];   // [1,M,3] fp32
    const float* planes = (const float*)d_in[2];   // [3,3,3] fp32
    const int*   bw     = (const int*)d_in[3];     // scalar box_warp

    int M = in_sizes[1] / 3;

    dim3 tg(HW / 64, PP);
    transpose_kernel<<<tg, 256>>>(feats, planes, bw);

    long long total = (long long)PP * M * 8;
    int blocks = (int)((total + 255) / 256);
    sample_kernel<<<blocks, 256>>>(coords, (float*)d_out, M);
}

// round 5
// speedup vs baseline: 1.1055x; 1.1055x over previous
#include <cuda_runtime.h>
#include <cuda_fp16.h>
#include <cstdint>

#define PP 3
#define CC 32
#define HH 256
#define WW 256
#define HW (HH * WW)

// Parity-duplicated, x-pair-interleaved fp16 texture (50.3 MB):
//   g_tex[p][par][y][b][c][e],  b = x-pair block (128/row), e = {west,east}
//   copy par covers pairs (2b+par, 2b+par+1); any x0 loads copy x0&1 aligned.
__device__ __align__(16) __half g_tex[PP * 2 * HH * 128 * CC * 2];
__device__ float g_inv[PP * 9];
__device__ float g_scale;

// ---------------------------------------------------------------------------
// Transpose: block = one (plane, y) row. Full 256-x row staged in smem so the
// odd-parity pairs never cross a tile boundary.
// ---------------------------------------------------------------------------
__global__ void __launch_bounds__(256) transpose_kernel(
    const float* __restrict__ in,
    const float* __restrict__ planes,
    const int* __restrict__ bw_raw) {
    if (blockIdx.x == 0 && blockIdx.y == 0 && threadIdx.x == 0) {
        int bits = bw_raw[0];
        float bw;
        if (bits > 0 && bits < 1000000) bw = (float)bits;          // int payload
        else                            bw = __int_as_float(bits); // float payload
        g_scale = 2.0f / bw;

        for (int p = 0; p < PP; p++) {
            const float* a = planes + p * 9;
            float a00=a[0],a01=a[1],a02=a[2];
            float a10=a[3],a11=a[4],a12=a[5];
            float a20=a[6],a21=a[7],a22=a[8];
            float c00 =  (a11*a22 - a12*a21);
            float c01 = -(a10*a22 - a12*a20);
            float c02 =  (a10*a21 - a11*a20);
            float c10 = -(a01*a22 - a02*a21);
            float c11 =  (a00*a22 - a02*a20);
            float c12 = -(a00*a21 - a01*a20);
            float c20 =  (a01*a12 - a02*a11);
            float c21 = -(a00*a12 - a02*a10);
            float c22 =  (a00*a11 - a01*a10);
            float det = a00*c00 + a01*c01 + a02*c02;
            float id  = 1.0f / det;
            float* o = g_inv + p * 9;
            o[0]=c00*id; o[1]=c10*id; o[2]=c20*id;
            o[3]=c01*id; o[4]=c11*id; o[5]=c21*id;
            o[6]=c02*id; o[7]=c12*id; o[8]=c22*id;
        }
    }

    __shared__ float tile[CC][257];      // full row, +1 pad
    int y   = blockIdx.x;                // row
    int p   = blockIdx.y;
    int tid = threadIdx.x;

    // Phase 1: read 32ch x 256x as float4 (coalesced along x)
    const float4* in4 = (const float4*)in + (size_t)p * CC * (HW / 4);
    int c = tid >> 3;                    // channel 0..31
    int f = tid & 7;                     // float4 slot
    #pragma unroll
    for (int r = 0; r < 8; r++) {
        int x4 = f + r * 8;              // 0..63
        float4 v = __ldg(in4 + (size_t)c * (HW / 4) + (size_t)y * 64 + x4);
        tile[c][4*x4 + 0] = v.x;
        tile[c][4*x4 + 1] = v.y;
        tile[c][4*x4 + 2] = v.z;
        tile[c][4*x4 + 3] = v.w;
    }
    __syncthreads();

    // Phase 2: emit both parity copies; consecutive tid -> consecutive channel
    // within a block -> 128B coalesced stores.
    __half2* dst = (__half2*)g_tex;
    #pragma unroll
    for (int r = 0; r < 32; r++) {
        int idx = r * 256 + tid;         // 0..8191
        int cc  = idx & 31;
        int b   = (idx >> 5) & 127;
        int par = idx >> 12;             // 0 or 1
        int xw  = 2*b + par;
        int xe  = min(xw + 1, WW - 1);
        __half2 h = __floats2half2_rn(tile[cc][xw], tile[cc][xe]);
        dst[(size_t)((p*2 + par)*HH + y) * 4096 + b * 32 + cc] = h;
    }
}

// ---------------------------------------------------------------------------
// Sampler: 4 lanes per (plane, point); lane q owns channels 8q..8q+7.
// Parity-duplicated texture -> each bilinear row is ONE aligned 32B load pair
// (two uint4) per lane; full bilinear computed in-lane. No shuffles, no PRMT.
// ---------------------------------------------------------------------------
__device__ __forceinline__ float2 h2f(unsigned u) {
    return __half22float2(*reinterpret_cast<__half2*>(&u));
}

__global__ void __launch_bounds__(256) sample_kernel(
    const float* __restrict__ coords, float* __restrict__ out, int M) {
    int t  = blockIdx.x * blockDim.x + threadIdx.x;
    int pm = t >> 2;
    int q  = t & 3;
    if (pm >= PP * M) return;

    int p = (pm >= 2*M) ? 2 : (pm >= M ? 1 : 0);
    int m = pm - p * M;

    float s = g_scale;
    const float* cp2 = coords + 3 * m;
    float x = __ldg(cp2)     * s;
    float y = __ldg(cp2 + 1) * s;
    float z = __ldg(cp2 + 2) * s;

    const float* inv = g_inv + p * 9;
    float u = x * inv[0] + y * inv[3] + z * inv[6];
    float v = x * inv[1] + y * inv[4] + z * inv[7];

    float ix = (u + 1.0f) * (0.5f * (WW - 1));
    float iy = (v + 1.0f) * (0.5f * (HH - 1));
    float fx = floorf(ix), fy = floorf(iy);

    float wxe = ix - fx;
    float wxw = (fx + 1.0f) - ix;
    float wys = iy - fy;
    float wyn = (fy + 1.0f) - iy;

    int fxi = (int)fx;
    int fyi = (int)fy;
    // x clamp folded onto the stored in-bounds pair
    if (fxi > WW - 2) { wxe = wxw + wxe; wxw = 0.0f; }
    if (fxi < 0)      { wxw = wxw + wxe; wxe = 0.0f; }
    int bx = min(max(fxi, 0), WW - 2);
    int y0 = min(max(fyi,     0), HH - 1);
    int y1 = min(max(fyi + 1, 0), HH - 1);

    float c0w = wyn * wxw, c0e = wyn * wxe;   // row y0
    float c1w = wys * wxw, c1e = wys * wxe;   // row y1

    int par = bx & 1;
    int xb  = bx >> 1;

    // uint4 view: one (par,y,block) = 8 uint4 (128B); lane q takes 2q, 2q+1
    const uint4* tex = (const uint4*)g_tex;
    size_t r0 = ((size_t)((p*2 + par)*HH + y0) * 128 + xb) * 8 + 2*q;
    size_t r1 = ((size_t)((p*2 + par)*HH + y1) * 128 + xb) * 8 + 2*q;
    uint4 u0a = __ldg(tex + r0);
    uint4 u0b = __ldg(tex + r0 + 1);
    uint4 u1a = __ldg(tex + r1);
    uint4 u1b = __ldg(tex + r1 + 1);

    float2 f0, f1;
    float4 rA, rB;
    f0 = h2f(u0a.x); f1 = h2f(u1a.x);
    rA.x = c0w*f0.x + c0e*f0.y + c1w*f1.x + c1e*f1.y;
    f0 = h2f(u0a.y); f1 = h2f(u1a.y);
    rA.y = c0w*f0.x + c0e*f0.y + c1w*f1.x + c1e*f1.y;
    f0 = h2f(u0a.z); f1 = h2f(u1a.z);
    rA.z = c0w*f0.x + c0e*f0.y + c1w*f1.x + c1e*f1.y;
    f0 = h2f(u0a.w); f1 = h2f(u1a.w);
    rA.w = c0w*f0.x + c0e*f0.y + c1w*f1.x + c1e*f1.y;

    f0 = h2f(u0b.x); f1 = h2f(u1b.x);
    rB.x = c0w*f0.x + c0e*f0.y + c1w*f1.x + c1e*f1.y;
    f0 = h2f(u0b.y); f1 = h2f(u1b.y);
    rB.y = c0w*f0.x + c0e*f0.y + c1w*f1.x + c1e*f1.y;
    f0 = h2f(u0b.z); f1 = h2f(u1b.z);
    rB.z = c0w*f0.x + c0e*f0.y + c1w*f1.x + c1e*f1.y;
    f0 = h2f(u0b.w); f1 = h2f(u1b.w);
    rB.w = c0w*f0.x + c0e*f0.y + c1w*f1.x + c1e*f1.y;

    // lane q owns channels 8q..8q+7 -> dense 128B per point, 1KB per warp
    float4* ob = (float4*)(out + (size_t)pm * CC);
    ob[2*q]     = rA;
    ob[2*q + 1] = rB;
}

// ---------------------------------------------------------------------------
extern "C" void kernel_launch(void* const* d_in, const int* in_sizes, int n_in,
                              void* d_out, int out_size) {
    const float* feats  = (const float*)d_in[0];   // [1,3,32,256,256] fp32
    const float* coords = (const float*)d_in[1];   // [1,M,3] fp32
    const float* planes = (const float*)d_in[2];   // [3,3,3] fp32
    const int*   bw     = (const int*)d_in[3];     // scalar box_warp

    int M = in_sizes[1] / 3;

    dim3 tg(HH, PP);
    transpose_kernel<<<tg, 256>>>(feats, planes, bw);

    long long total = (long long)PP * M * 4;
    int blocks = (int)((total + 255) / 256);
    sample_kernel<<<blocks, 256>>>(coords, (float*)d_out, M);
}